// round 13
// baseline (speedup 1.0000x reference)
#include <cuda_runtime.h>
#include <cuda_fp16.h>
#include <cstdint>
#include <cstddef>

#define BB 2
#define QQ 512
#define KK 512
#define TT 256

// ---------------- scratch (device globals; no allocation) ----------------
__device__ __half g_z[(size_t)BB * KK * TT * QQ];   // [b][i][u][j'] j-permuted (8-half2 window transpose)
__device__ float  g_kproj[BB * KK * TT];            // k projection (fp32)
__device__ __half g_qh[BB * QQ * TT];               // q projection, PRE-SWIZZLED 32j-chunk layout
__device__ float  g_v[BB * KK * TT];                // v projection (fp32)
__device__ float  g_w[BB * KK * TT];                // v / (sum|z| + e^m)
__device__ float  g_opre[BB * QQ * TT];             // pre-Wvo output

#define DINL __device__ __forceinline__

DINL uint32_t smem_u32(const void* p) {
    uint32_t a;
    asm("{ .reg .u64 t; cvta.to.shared.u64 t, %1; cvt.u32.u64 %0, t; }" : "=r"(a) : "l"(p));
    return a;
}

DINL void ldsm4(uint32_t& r0, uint32_t& r1, uint32_t& r2, uint32_t& r3, uint32_t addr) {
    asm volatile("ldmatrix.sync.aligned.m8n8.x4.shared.b16 {%0,%1,%2,%3}, [%4];"
                 : "=r"(r0), "=r"(r1), "=r"(r2), "=r"(r3) : "r"(addr));
}

DINL void mma16816(float* c, const uint32_t* a, const uint32_t* b) {
    asm volatile(
        "mma.sync.aligned.m16n8k16.row.col.f32.f16.f16.f32 "
        "{%0,%1,%2,%3}, {%4,%5,%6,%7}, {%8,%9}, {%0,%1,%2,%3};"
        : "+f"(c[0]), "+f"(c[1]), "+f"(c[2]), "+f"(c[3])
        : "r"(a[0]), "r"(a[1]), "r"(a[2]), "r"(a[3]), "r"(b[0]), "r"(b[1]));
}

// ---- sm_90 bulk-copy + mbarrier (plain compute_103-legal PTX) ----
DINL void mbar_init(uint32_t mbar, uint32_t cnt) {
    asm volatile("mbarrier.init.shared.b64 [%0], %1;" :: "r"(mbar), "r"(cnt) : "memory");
}
DINL void mbar_expect_tx(uint32_t mbar, uint32_t bytes) {
    asm volatile("mbarrier.arrive.expect_tx.shared.b64 _, [%0], %1;"
                 :: "r"(mbar), "r"(bytes) : "memory");
}
DINL void bulk_copy_g2s(uint32_t sdst, const void* gsrc, uint32_t bytes, uint32_t mbar) {
    asm volatile(
        "cp.async.bulk.shared::cluster.global.mbarrier::complete_tx::bytes [%0], [%1], %2, [%3];"
        :: "r"(sdst), "l"(gsrc), "r"(bytes), "r"(mbar) : "memory");
}
DINL void mbar_wait(uint32_t mbar, uint32_t parity) {
    asm volatile(
        "{\n\t.reg .pred P;\n\tW%=:\n\t"
        "mbarrier.try_wait.parity.shared::cta.b64 P, [%0], %1, 0x989680;\n\t"
        "@!P bra.uni W%=;\n\t}"
        :: "r"(mbar), "r"(parity) : "memory");
}
DINL void fence_async() { asm volatile("fence.proxy.async.shared::cta;" ::: "memory"); }

DINL uint32_t pack2h(float a, float b) {
    __half2 h = __halves2half2(__float2half_rn(a), __float2half_rn(b));
    return *reinterpret_cast<uint32_t*>(&h);
}

// ---------------- projection GEMM body: out[r,u] = sum_t X[r,t]*W[u,t] ----------------
template <int MODE>
DINL void proj_body(const float* __restrict__ X, const float* __restrict__ W,
                    float* __restrict__ out_ext, int rb, int ub) {
    __shared__ float xs[32][33];
    __shared__ float ws[64][33];
    int tid = threadIdx.x;
    int r = tid & 31, u0 = (tid >> 5) * 8;
    float acc[8];
#pragma unroll
    for (int e = 0; e < 8; e++) acc[e] = 0.f;

    for (int t0 = 0; t0 < TT; t0 += 32) {
#pragma unroll
        for (int l = 0; l < 4; l++) {
            int idx = tid + l * 256; int row = idx >> 5, col = idx & 31;
            xs[row][col] = X[(rb + row) * TT + t0 + col];
        }
#pragma unroll
        for (int l = 0; l < 8; l++) {
            int idx = tid + l * 256; int row = idx >> 5, col = idx & 31;
            ws[row][col] = W[(ub + row) * TT + t0 + col];
        }
        __syncthreads();
#pragma unroll
        for (int tt = 0; tt < 32; tt++) {
            float xv = xs[r][tt];
#pragma unroll
            for (int e = 0; e < 8; e++) acc[e] += xv * ws[u0 + e][tt];
        }
        __syncthreads();
    }
    if (MODE == 1) {
        // q projection -> PRE-SWIZZLED 32j-chunk layout:
        // half idx = ((b*16 + cch)*32 + rr)*256 + ((grp ^ (rr&7))*8 + t%8)
        int rg = rb + r;
        int bb2 = rg >> 9, j = rg & 511;
        int cch = j >> 5, rr = j & 31;
        int grp = (ub + u0) >> 3;
        uint32_t hoff = ((uint32_t)((bb2 * 16 + cch) * 32 + rr)) * 256u
                        + (uint32_t)((grp ^ (rr & 7)) << 3);
        uint4 v;
        v.x = pack2h(acc[0], acc[1]);
        v.y = pack2h(acc[2], acc[3]);
        v.z = pack2h(acc[4], acc[5]);
        v.w = pack2h(acc[6], acc[7]);
        *reinterpret_cast<uint4*>(g_qh + hoff) = v;
    } else {
#pragma unroll
        for (int e = 0; e < 8; e++) {
            int o = (rb + r) * TT + ub + u0 + e;
            if (MODE == 0)      g_kproj[o] = acc[e];
            else if (MODE == 2) g_v[o]     = acc[e];
            else                out_ext[o] = acc[e];
        }
    }
}

// fused k/q/v projections: blockIdx.z selects which
__global__ void __launch_bounds__(256) proj3_kernel(const float* __restrict__ q_t,
                                                    const float* __restrict__ k_t,
                                                    const float* __restrict__ v_t,
                                                    const float* __restrict__ Wk,
                                                    const float* __restrict__ Wq,
                                                    const float* __restrict__ Wva) {
    int rb = blockIdx.x * 32, ub = blockIdx.y * 64;
    if (blockIdx.z == 0)      proj_body<0>(k_t, Wk,  nullptr, rb, ub);
    else if (blockIdx.z == 1) proj_body<1>(q_t, Wq,  nullptr, rb, ub);
    else                      proj_body<2>(v_t, Wva, nullptr, rb, ub);
}

// final projection: out = g_opre @ Wvo^T
__global__ void __launch_bounds__(256) projo_kernel(const float* __restrict__ W,
                                                    float* __restrict__ out_ext) {
    proj_body<3>(g_opre, W, out_ext, blockIdx.x * 32, blockIdx.y * 64);
}

// ---------------- core kernel (2 CTAs/SM) ----------------
// SMEM: A slab [0,64K) persistent, B ring 2x16K at [64K,96K), mbars at 96K
#define S_BRING 65536
#define S_MB    98304
#define S_TOTAL 98320
#define CHUNK_BYTES 16384u
#define NCHUNK 16

__global__ void __launch_bounds__(256, 2) attn_core(const float* __restrict__ Wal) {
    extern __shared__ char smem[];
    uint32_t sb = smem_u32(smem);
    const int tid = threadIdx.x;
    const int lane = tid & 31;
    const int wid = tid >> 5;
    const int warp_m = wid >> 1;   // 0..3  (32 u-rows each)
    const int warp_n = wid & 1;    // 0..1  (16 j-cols each)

    const int bx = blockIdx.x;
    const int uh = bx & 1;
    const int i  = (bx >> 1) & 511;
    const int b  = bx >> 10;

    // ---- tid0: init mbarriers, kick prologue copies (chunks 0,1) ----
    const __half* __restrict__ qsw = g_qh + (size_t)b * QQ * TT;
    if (tid == 0) {
        mbar_init(sb + S_MB, 1);
        mbar_init(sb + S_MB + 8, 1);
        fence_async();
#pragma unroll
        for (int m = 0; m < 2; m++) {
            mbar_expect_tx(sb + S_MB + m * 8, CHUNK_BYTES);
            bulk_copy_g2s(sb + S_BRING + m * CHUNK_BYTES, qsw + (size_t)m * 32 * 256,
                          CHUNK_BYTES, sb + S_MB + m * 8);
        }
    }

    const float* __restrict__ walr = Wal + (size_t)uh * 128 * TT;
    const float* __restrict__ kp   = g_kproj + (b * KK + i) * TT;

    // ---- build A = fp16(Wal[u_half,:] * k_i[:]) in persistent smem slab ----
#pragma unroll
    for (int it = 0; it < 16; it++) {
        int idx = tid + it * 256;
        int row = idx >> 5, cc = idx & 31;
        int t0 = cc * 8;
        float4 w0 = *reinterpret_cast<const float4*>(walr + row * TT + t0);
        float4 w1 = *reinterpret_cast<const float4*>(walr + row * TT + t0 + 4);
        float4 k0 = __ldg(reinterpret_cast<const float4*>(kp + t0));
        float4 k1 = __ldg(reinterpret_cast<const float4*>(kp + t0 + 4));
        uint4 v;
        v.x = pack2h(w0.x * k0.x, w0.y * k0.y);
        v.y = pack2h(w0.z * k0.z, w0.w * k0.w);
        v.z = pack2h(w1.x * k1.x, w1.y * k1.y);
        v.w = pack2h(w1.z * k1.z, w1.w * k1.w);
        uint32_t off = (uint32_t)(row * 512 + ((cc ^ (row & 7)) << 4));
        *reinterpret_cast<uint4*>(smem + off) = v;
    }
    __syncthreads();   // A staged AND mbarriers published

    // A ldsm addressing (re-read per chunk; warp owns u-rows [warp_m*32,+32))
    const int cbitA = lane >> 4;
    uint32_t amBase0, amBase1; int xA0, xA1;
    {
        int rowA0 = warp_m * 32 + (lane & 15);
        int rowA1 = rowA0 + 16;
        amBase0 = sb + (uint32_t)rowA0 * 512; xA0 = rowA0 & 7;
        amBase1 = sb + (uint32_t)rowA1 * 512; xA1 = rowA1 & 7;
    }

    // B ldsm addressing (warp reads j in [warp_n*16,+16): ONE ldsm.x4 per ks)
    const int cbitB = (lane >> 3) & 1;
    const int rowB = warp_n * 16 + (lane & 7) + ((lane >> 4) << 3);
    const uint32_t bBase = (uint32_t)rowB * 512;
    const int xB = rowB & 7;

    // z store base: PERMUTED — thread's 2 half2 (g=0,1) contiguous at (lane&3)*4 halves
    const size_t zbase = ((size_t)((b * KK + i) * TT + uh * 128)) * QQ
                         + warp_n * 16 + (lane & 3) * 4;
    const int urow0 = warp_m * 32 + (lane >> 2);   // + mf*16 + h*8
    float m4[2][2] = {{-3.0e38f, -3.0e38f}, {-3.0e38f, -3.0e38f}};
    float s4[2][2] = {{0.f, 0.f}, {0.f, 0.f}};

#pragma unroll 1
    for (int c = 0; c < NCHUNK; c++) {
        const uint32_t slot = (uint32_t)(c & 1);
        mbar_wait(sb + S_MB + slot * 8, (uint32_t)((c >> 1) & 1));
        const uint32_t bb = sb + S_BRING + slot * CHUNK_BYTES;

        float acc[2][2][4];   // [mf][g][x] — 16 regs, single-buffered
#pragma unroll
        for (int mf = 0; mf < 2; mf++)
#pragma unroll
            for (int g = 0; g < 2; g++)
#pragma unroll
                for (int x = 0; x < 4; x++) acc[mf][g][x] = 0.f;

#pragma unroll
        for (int ks = 0; ks < 16; ks++) {
            uint32_t bfr[4];
            ldsm4(bfr[0], bfr[1], bfr[2], bfr[3],
                  bb + bBase + (uint32_t)(((2 * ks + cbitB) ^ xB) << 4));
            uint32_t at[8];
            ldsm4(at[0], at[1], at[2], at[3],
                  amBase0 + (uint32_t)(((2 * ks + cbitA) ^ xA0) << 4));
            ldsm4(at[4], at[5], at[6], at[7],
                  amBase1 + (uint32_t)(((2 * ks + cbitA) ^ xA1) << 4));
#pragma unroll
            for (int mf = 0; mf < 2; mf++)
#pragma unroll
                for (int g = 0; g < 2; g++)
                    mma16816(acc[mf][g], &at[mf * 4], &bfr[g * 2]);
        }

        // ---- epilogue: z = l*e^l; 8B coalesced store; running (m, sum|z|) ----
#pragma unroll
        for (int mf = 0; mf < 2; mf++) {
#pragma unroll
            for (int h = 0; h < 2; h++) {
                uint2 v;
                uint32_t* pv = &v.x;
#pragma unroll
                for (int g = 0; g < 2; g++) {
                    float l0 = acc[mf][g][h * 2 + 0];
                    float l1 = acc[mf][g][h * 2 + 1];
                    float e0 = __expf(l0);
                    float e1 = __expf(l1);
                    s4[mf][h] = fmaf(fabsf(l0), e0, s4[mf][h]);
                    s4[mf][h] = fmaf(fabsf(l1), e1, s4[mf][h]);
                    m4[mf][h] = fmaxf(m4[mf][h], fmaxf(l0, l1));
                    pv[g] = pack2h(l0 * e0, l1 * e1);
                }
                __half* zr = g_z + zbase + (size_t)(urow0 + mf * 16 + h * 8) * QQ + c * 32;
                __stcs(reinterpret_cast<uint2*>(zr), v);
            }
        }

        __syncthreads();   // buffer consumed by all warps
        if (c + 2 < NCHUNK && tid == 0) {
            uint32_t mb = sb + S_MB + slot * 8;
            mbar_expect_tx(mb, CHUNK_BYTES);
            bulk_copy_g2s(bb, qsw + (size_t)(c + 2) * 32 * 256, CHUNK_BYTES, mb);
        }
    }

    // ---- (m,s): reduce across quad (j) then across the 2 n-warps via smem ----
#pragma unroll
    for (int mf = 0; mf < 2; mf++)
#pragma unroll
        for (int h = 0; h < 2; h++) {
#pragma unroll
            for (int off = 1; off <= 2; off <<= 1) {
                m4[mf][h] = fmaxf(m4[mf][h], __shfl_xor_sync(0xFFFFFFFFu, m4[mf][h], off));
                s4[mf][h] += __shfl_xor_sync(0xFFFFFFFFu, s4[mf][h], off);
            }
        }
    float2* red = reinterpret_cast<float2*>(smem);   // A slab dead now
    __syncthreads();
    if ((lane & 3) == 0) {
#pragma unroll
        for (int mf = 0; mf < 2; mf++)
#pragma unroll
            for (int h = 0; h < 2; h++) {
                int u_local = warp_m * 32 + mf * 16 + h * 8 + (lane >> 2);
                red[warp_n * 128 + u_local] = make_float2(m4[mf][h], s4[mf][h]);
            }
    }
    __syncthreads();
    if (tid < 128) {
        float2 p0 = red[tid];
        float2 p1 = red[128 + tid];
        float mv = fmaxf(p0.x, p1.x);
        float sv = p0.y + p1.y;
        int u = uh * 128 + tid;
        int vi = (b * KK + i) * TT + u;
        g_w[vi] = g_v[vi] / (sv + __expf(mv));
    }
}

// ---------------- combine: out_pre[b,j,u] = sum_i w[b,i,u] * z[b,i,u,j'] ----------------
// z rows j-PERMUTED: within each 8-half2 window, logical j2 = (s&1)*4 + (s>>1), s = jh&7.
__global__ void __launch_bounds__(512) combine_kernel() {
    __shared__ float ws[2][KK];
    int u0 = blockIdx.x * 2, b = blockIdx.y;
    int tid = threadIdx.x;
    for (int idx = tid; idx < 2 * KK; idx += 512)
        ws[idx >> 9][idx & 511] = g_w[(b * KK + (idx & 511)) * TT + u0 + (idx >> 9)];
    __syncthreads();

    int uo = tid >> 8, jh = tid & 255;
    int u = u0 + uo;
    const __half2* zp = reinterpret_cast<const __half2*>(g_z)
                        + ((size_t)(b * KK * TT + u)) * (QQ / 2) + jh;
    const float* wsu = ws[uo];
    float accx = 0.f, accy = 0.f;
#pragma unroll 8
    for (int i = 0; i < KK; i++) {
        __half2 zz = __ldcs(zp);
        float2 zf = __half22float2(zz);
        float wv = wsu[i];
        accx += wv * zf.x;
        accy += wv * zf.y;
        zp += (size_t)TT * (QQ / 2);
    }
    // invert the store permutation within each 8-half2 window
    int s = jh & 7;
    int j2 = (jh & ~7) | ((s & 1) * 4 + (s >> 1));
    int j = j2 * 2;
    g_opre[(b * QQ + j) * TT + u]     = accx;
    g_opre[(b * QQ + j + 1) * TT + u] = accy;
}

// ---------------- launch ----------------
extern "C" void kernel_launch(void* const* d_in, const int* in_sizes, int n_in,
                              void* d_out, int out_size) {
    const float* q_t = (const float*)d_in[0];
    const float* k_t = (const float*)d_in[1];
    const float* v_t = (const float*)d_in[2];
    const float* Wk  = (const float*)d_in[3];
    const float* Wq  = (const float*)d_in[4];
    const float* Wva = (const float*)d_in[5];
    const float* Wal = (const float*)d_in[6];
    const float* Wvo = (const float*)d_in[7];
    float* out = (float*)d_out;

    cudaFuncSetAttribute(attn_core, cudaFuncAttributeMaxDynamicSharedMemorySize, S_TOTAL);

    proj3_kernel<<<dim3(32, 4, 3), 256>>>(q_t, k_t, v_t, Wk, Wq, Wva);

    attn_core<<<BB * KK * 2, 256, S_TOTAL>>>(Wal);

    combine_kernel<<<dim3(QQ / 4, BB), 512>>>();

    projo_kernel<<<dim3(32, 4), 256>>>(Wvo, out);
}

// round 14
// speedup vs baseline: 1.1618x; 1.1618x over previous
#include <cuda_runtime.h>
#include <cuda_fp16.h>
#include <cstdint>
#include <cstddef>

#define BB 2
#define QQ 512
#define KK 512
#define TT 256

// ---------------- scratch (device globals; no allocation) ----------------
__device__ __half g_z[(size_t)BB * KK * TT * QQ];   // [b][i][u][j']  j-permuted (4x4 transpose per 16-half2 window)
__device__ float  g_kproj[BB * KK * TT];            // k projection (fp32)
__device__ __half g_qh[BB * QQ * TT];               // q projection, PRE-SWIZZLED 64j-chunk layout
__device__ float  g_v[BB * KK * TT];                // v projection (fp32)
__device__ float  g_w[BB * KK * TT];                // v / (sum|z| + e^m)
__device__ float  g_opre[BB * QQ * TT];             // pre-Wvo output

#define DINL __device__ __forceinline__

DINL uint32_t smem_u32(const void* p) {
    uint32_t a;
    asm("{ .reg .u64 t; cvta.to.shared.u64 t, %1; cvt.u32.u64 %0, t; }" : "=r"(a) : "l"(p));
    return a;
}

DINL void ldsm4(uint32_t& r0, uint32_t& r1, uint32_t& r2, uint32_t& r3, uint32_t addr) {
    asm volatile("ldmatrix.sync.aligned.m8n8.x4.shared.b16 {%0,%1,%2,%3}, [%4];"
                 : "=r"(r0), "=r"(r1), "=r"(r2), "=r"(r3) : "r"(addr));
}

DINL void mma16816(float* c, const uint32_t* a, const uint32_t* b) {
    asm volatile(
        "mma.sync.aligned.m16n8k16.row.col.f32.f16.f16.f32 "
        "{%0,%1,%2,%3}, {%4,%5,%6,%7}, {%8,%9}, {%0,%1,%2,%3};"
        : "+f"(c[0]), "+f"(c[1]), "+f"(c[2]), "+f"(c[3])
        : "r"(a[0]), "r"(a[1]), "r"(a[2]), "r"(a[3]), "r"(b[0]), "r"(b[1]));
}

// ---- sm_90 bulk-copy + mbarrier (plain compute_103-legal PTX) ----
DINL void mbar_init(uint32_t mbar, uint32_t cnt) {
    asm volatile("mbarrier.init.shared.b64 [%0], %1;" :: "r"(mbar), "r"(cnt) : "memory");
}
DINL void mbar_expect_tx(uint32_t mbar, uint32_t bytes) {
    asm volatile("mbarrier.arrive.expect_tx.shared.b64 _, [%0], %1;"
                 :: "r"(mbar), "r"(bytes) : "memory");
}
DINL void bulk_copy_g2s(uint32_t sdst, const void* gsrc, uint32_t bytes, uint32_t mbar) {
    asm volatile(
        "cp.async.bulk.shared::cluster.global.mbarrier::complete_tx::bytes [%0], [%1], %2, [%3];"
        :: "r"(sdst), "l"(gsrc), "r"(bytes), "r"(mbar) : "memory");
}
DINL void mbar_wait(uint32_t mbar, uint32_t parity) {
    asm volatile(
        "{\n\t.reg .pred P;\n\tW%=:\n\t"
        "mbarrier.try_wait.parity.shared::cta.b64 P, [%0], %1, 0x989680;\n\t"
        "@!P bra.uni W%=;\n\t}"
        :: "r"(mbar), "r"(parity) : "memory");
}
DINL void fence_async() { asm volatile("fence.proxy.async.shared::cta;" ::: "memory"); }

DINL uint32_t pack2h(float a, float b) {
    __half2 h = __halves2half2(__float2half_rn(a), __float2half_rn(b));
    return *reinterpret_cast<uint32_t*>(&h);
}

// ---------------- projection GEMM body: out[r,u] = sum_t X[r,t]*W[u,t] ----------------
template <int MODE>
DINL void proj_body(const float* __restrict__ X, const float* __restrict__ W,
                    int rb, int ub) {
    __shared__ float xs[32][33];
    __shared__ float ws[64][33];
    int tid = threadIdx.x;
    int r = tid & 31, u0 = (tid >> 5) * 8;
    float acc[8];
#pragma unroll
    for (int e = 0; e < 8; e++) acc[e] = 0.f;

    for (int t0 = 0; t0 < TT; t0 += 32) {
#pragma unroll
        for (int l = 0; l < 4; l++) {
            int idx = tid + l * 256; int row = idx >> 5, col = idx & 31;
            xs[row][col] = X[(rb + row) * TT + t0 + col];
        }
#pragma unroll
        for (int l = 0; l < 8; l++) {
            int idx = tid + l * 256; int row = idx >> 5, col = idx & 31;
            ws[row][col] = W[(ub + row) * TT + t0 + col];
        }
        __syncthreads();
#pragma unroll
        for (int tt = 0; tt < 32; tt++) {
            float xv = xs[r][tt];
#pragma unroll
            for (int e = 0; e < 8; e++) acc[e] += xv * ws[u0 + e][tt];
        }
        __syncthreads();
    }
    if (MODE == 1) {
        // q projection -> PRE-SWIZZLED 64j-chunk layout
        int rg = rb + r;
        int bb2 = rg >> 9, j = rg & 511;
        int cch = j >> 6, rr = j & 63;
        int grp = (ub + u0) >> 3;
        uint32_t hoff = ((uint32_t)((bb2 * 8 + cch) * 64 + rr)) * 256u
                        + (uint32_t)((grp ^ (rr & 7)) << 3);
        uint4 v;
        v.x = pack2h(acc[0], acc[1]);
        v.y = pack2h(acc[2], acc[3]);
        v.z = pack2h(acc[4], acc[5]);
        v.w = pack2h(acc[6], acc[7]);
        *reinterpret_cast<uint4*>(g_qh + hoff) = v;
    } else {
#pragma unroll
        for (int e = 0; e < 8; e++) {
            int o = (rb + r) * TT + ub + u0 + e;
            if (MODE == 0)      g_kproj[o] = acc[e];
            else                g_v[o]     = acc[e];
        }
    }
}

// fused k/q/v projections: blockIdx.z selects which
__global__ void __launch_bounds__(256) proj3_kernel(const float* __restrict__ q_t,
                                                    const float* __restrict__ k_t,
                                                    const float* __restrict__ v_t,
                                                    const float* __restrict__ Wk,
                                                    const float* __restrict__ Wq,
                                                    const float* __restrict__ Wva) {
    int rb = blockIdx.x * 32, ub = blockIdx.y * 64;
    if (blockIdx.z == 0)      proj_body<0>(k_t, Wk,  rb, ub);
    else if (blockIdx.z == 1) proj_body<1>(q_t, Wq,  rb, ub);
    else                      proj_body<2>(v_t, Wva, rb, ub);
}

// final projection: out = g_opre @ Wvo^T — 32x32 tiles, 256 blocks (latency-bound fix)
__global__ void __launch_bounds__(256) projo_kernel(const float* __restrict__ W,
                                                    float* __restrict__ out_ext) {
    __shared__ float xs[32][33];
    __shared__ float ws[32][33];
    int rb = blockIdx.x * 32, ub = blockIdx.y * 32;
    int tid = threadIdx.x;
    int r = tid & 31, u0 = (tid >> 5) * 4;
    float acc[4] = {0.f, 0.f, 0.f, 0.f};

    for (int t0 = 0; t0 < TT; t0 += 32) {
#pragma unroll
        for (int l = 0; l < 4; l++) {
            int idx = tid + l * 256; int row = idx >> 5, col = idx & 31;
            xs[row][col] = g_opre[(rb + row) * TT + t0 + col];
        }
#pragma unroll
        for (int l = 0; l < 4; l++) {
            int idx = tid + l * 256; int row = idx >> 5, col = idx & 31;
            ws[row][col] = W[(ub + row) * TT + t0 + col];
        }
        __syncthreads();
#pragma unroll
        for (int tt = 0; tt < 32; tt++) {
            float xv = xs[r][tt];
#pragma unroll
            for (int e = 0; e < 4; e++) acc[e] += xv * ws[u0 + e][tt];
        }
        __syncthreads();
    }
#pragma unroll
    for (int e = 0; e < 4; e++)
        out_ext[(rb + r) * TT + ub + u0 + e] = acc[e];
}

// ---------------- core kernel (exact 297.7us configuration) ----------------
// SMEM: A slab [0,64K) persistent, B ring 4x32K at [64K,192K), mbars at 192K
#define S_BRING 65536
#define S_MB    196608
#define S_TOTAL 196672
#define CHUNK_BYTES 32768u

__global__ void __launch_bounds__(256, 1) attn_core(const float* __restrict__ Wal) {
    extern __shared__ char smem[];
    uint32_t sb = smem_u32(smem);
    const int tid = threadIdx.x;
    const int lane = tid & 31;
    const int wid = tid >> 5;
    const int warp_m = wid >> 1;   // 0..3  (32 u-rows each)
    const int warp_n = wid & 1;    // 0..1  (32 j-cols each)

    const int bx = blockIdx.x;
    const int uh = bx & 1;
    const int i  = (bx >> 1) & 511;
    const int b  = bx >> 10;

    // ---- tid0: init mbarriers, then kick ALL 4 prologue copies ----
    const __half* __restrict__ qsw = g_qh + (size_t)(b * 8) * 64 * 256;
    if (tid == 0) {
#pragma unroll
        for (int m = 0; m < 4; m++) mbar_init(sb + S_MB + m * 8, 1);
        fence_async();
#pragma unroll
        for (int m = 0; m < 4; m++) {
            mbar_expect_tx(sb + S_MB + m * 8, CHUNK_BYTES);
            bulk_copy_g2s(sb + S_BRING + m * CHUNK_BYTES, qsw + (size_t)m * 64 * 256,
                          CHUNK_BYTES, sb + S_MB + m * 8);
        }
    }

    const float* __restrict__ walr = Wal + (size_t)uh * 128 * TT;
    const float* __restrict__ kp   = g_kproj + (b * KK + i) * TT;

    // ---- build A = fp16(Wal[u_half,:] * k_i[:]) in persistent smem slab ----
#pragma unroll
    for (int it = 0; it < 16; it++) {
        int idx = tid + it * 256;
        int row = idx >> 5, cc = idx & 31;
        int t0 = cc * 8;
        float4 w0 = *reinterpret_cast<const float4*>(walr + row * TT + t0);
        float4 w1 = *reinterpret_cast<const float4*>(walr + row * TT + t0 + 4);
        float4 k0 = __ldg(reinterpret_cast<const float4*>(kp + t0));
        float4 k1 = __ldg(reinterpret_cast<const float4*>(kp + t0 + 4));
        uint4 v;
        v.x = pack2h(w0.x * k0.x, w0.y * k0.y);
        v.y = pack2h(w0.z * k0.z, w0.w * k0.w);
        v.z = pack2h(w1.x * k1.x, w1.y * k1.y);
        v.w = pack2h(w1.z * k1.z, w1.w * k1.w);
        uint32_t off = (uint32_t)(row * 512 + ((cc ^ (row & 7)) << 4));
        *reinterpret_cast<uint4*>(smem + off) = v;
    }
    __syncthreads();   // A staged AND mbarriers published

    // A addressing; ks 0..7 fragments resident in regs, ks 8..15 re-ldsm'd per chunk
    const int cbitA = lane >> 4;
    uint32_t amBase[2]; int xA[2];
#pragma unroll
    for (int mf = 0; mf < 2; mf++) {
        int rowA = warp_m * 32 + mf * 16 + (lane & 15);
        amBase[mf] = sb + (uint32_t)rowA * 512;
        xA[mf] = rowA & 7;
    }
    uint32_t ahi[2][32];   // 64 regs: ks 0..7
#pragma unroll
    for (int mf = 0; mf < 2; mf++)
#pragma unroll
        for (int ks = 0; ks < 8; ks++)
            ldsm4(ahi[mf][ks * 4], ahi[mf][ks * 4 + 1], ahi[mf][ks * 4 + 2], ahi[mf][ks * 4 + 3],
                  amBase[mf] + (uint32_t)(((2 * ks + cbitA) ^ xA[mf]) << 4));

    // B ldmatrix lane addressing (warp reads j in [warp_n*32, +32))
    uint32_t bBase[2]; int xB[2];
    const int cbitB = (lane >> 3) & 1;
#pragma unroll
    for (int e = 0; e < 2; e++) {
        int rowB = warp_n * 32 + e * 16 + (lane & 7) + ((lane >> 4) << 3);
        bBase[e] = (uint32_t)(rowB * 512);
        xB[e] = rowB & 7;
    }

    // z store base: PERMUTED layout — thread's 4 half2 go contiguously (16B) at (lane&3)*8
    const size_t zbase = ((size_t)((b * KK + i) * TT + uh * 128)) * QQ
                         + warp_n * 32 + (lane & 3) * 8;
    const int urow0 = warp_m * 32 + (lane >> 2);   // + mf*16 + h*8
    float m4[2][2] = {{-3.0e38f, -3.0e38f}, {-3.0e38f, -3.0e38f}};
    float s4[2][2] = {{0.f, 0.f}, {0.f, 0.f}};

    // two STATICALLY-NAMED accumulator buffers (never runtime-indexed -> stay in regs)
    float accA[2][4][4], accB[2][4][4];

    // one epilogue unit: chunk cp, (mf,h) slice -> 4 half2 packed into ONE uint4 store
    auto epi_unit = [&](int cp, const float (&a)[2][4][4], int mf, int h) {
        uint4 v;
        uint32_t* pv = &v.x;
#pragma unroll
        for (int g = 0; g < 4; g++) {
            float l0 = a[mf][g][h * 2 + 0];
            float l1 = a[mf][g][h * 2 + 1];
            float e0 = __expf(l0);
            float e1 = __expf(l1);
            s4[mf][h] = fmaf(fabsf(l0), e0, s4[mf][h]);
            s4[mf][h] = fmaf(fabsf(l1), e1, s4[mf][h]);
            m4[mf][h] = fmaxf(m4[mf][h], fmaxf(l0, l1));
            pv[g] = pack2h(l0 * e0, l1 * e1);
        }
        __half* zr = g_z + zbase + (size_t)(urow0 + mf * 16 + h * 8) * QQ + cp * 64;
        __stcs(reinterpret_cast<uint4*>(zr), v);
    };

    // MMA of chunk c into accC, with epilogue of chunk cp (accP) fused per-4-ks.
    auto run_chunk = [&](int c, float (&accC)[2][4][4],
                         const float (&accP)[2][4][4], bool doEpi, int cp) {
        mbar_wait(sb + S_MB + (c & 3) * 8, (uint32_t)((c >> 2) & 1));
        const uint32_t bb = sb + S_BRING + (c & 3) * CHUNK_BYTES;
#pragma unroll
        for (int mf = 0; mf < 2; mf++)
#pragma unroll
            for (int g = 0; g < 4; g++)
#pragma unroll
                for (int x = 0; x < 4; x++) accC[mf][g][x] = 0.f;

#pragma unroll
        for (int ks = 0; ks < 16; ks++) {
            uint32_t bfr[8];
#pragma unroll
            for (int e = 0; e < 2; e++)
                ldsm4(bfr[e * 4], bfr[e * 4 + 1], bfr[e * 4 + 2], bfr[e * 4 + 3],
                      bb + bBase[e] + (uint32_t)(((2 * ks + cbitB) ^ xB[e]) << 4));
            if (ks < 8) {
#pragma unroll
                for (int mf = 0; mf < 2; mf++)
#pragma unroll
                    for (int g = 0; g < 4; g++)
                        mma16816(accC[mf][g], &ahi[mf][ks * 4], &bfr[2 * g]);
            } else {
                uint32_t at[8];
#pragma unroll
                for (int mf = 0; mf < 2; mf++)
                    ldsm4(at[mf * 4], at[mf * 4 + 1], at[mf * 4 + 2], at[mf * 4 + 3],
                          amBase[mf] + (uint32_t)(((2 * ks + cbitA) ^ xA[mf]) << 4));
#pragma unroll
                for (int mf = 0; mf < 2; mf++)
#pragma unroll
                    for (int g = 0; g < 4; g++)
                        mma16816(accC[mf][g], &at[mf * 4], &bfr[2 * g]);
            }
            if (doEpi && (ks & 3) == 3)   // fused epilogue unit (fills HMMA gaps)
                epi_unit(cp, accP, ks >> 3, (ks >> 2) & 1);
        }
    };

    // ---- pair loop: compile-time acc buffer roles; epilogue always one chunk behind ----
#pragma unroll 1
    for (int p = 0; p < 4; p++) {
        int c0 = 2 * p, c1 = 2 * p + 1;
        run_chunk(c0, accA, accB, p > 0, c0 - 1);  // epi of chunk 2p-1 (accB)
        run_chunk(c1, accB, accA, true,  c0);      // epi of chunk 2p   (accA)

        __syncthreads();   // pair buffers fully consumed by all warps
        if (p < 2 && tid == 0) {
#pragma unroll
            for (int e = 0; e < 2; e++) {
                int cn = 2 * p + 4 + e;    // refill the two freed buffers
                uint32_t mb = sb + S_MB + (cn & 3) * 8;
                mbar_expect_tx(mb, CHUNK_BYTES);
                bulk_copy_g2s(sb + S_BRING + (cn & 3) * CHUNK_BYTES,
                              qsw + (size_t)cn * 64 * 256, CHUNK_BYTES, mb);
            }
        }
    }
    // drain epilogue of chunk 7 (accB)
#pragma unroll
    for (int u = 0; u < 4; u++)
        epi_unit(7, accB, u >> 1, u & 1);

    // ---- (m,s): reduce across quad (j) then across the 2 n-warps via smem ----
#pragma unroll
    for (int mf = 0; mf < 2; mf++)
#pragma unroll
        for (int h = 0; h < 2; h++) {
#pragma unroll
            for (int off = 1; off <= 2; off <<= 1) {
                m4[mf][h] = fmaxf(m4[mf][h], __shfl_xor_sync(0xFFFFFFFFu, m4[mf][h], off));
                s4[mf][h] += __shfl_xor_sync(0xFFFFFFFFu, s4[mf][h], off);
            }
        }
    float2* red = reinterpret_cast<float2*>(smem);   // A slab dead now
    __syncthreads();
    if ((lane & 3) == 0) {
#pragma unroll
        for (int mf = 0; mf < 2; mf++)
#pragma unroll
            for (int h = 0; h < 2; h++) {
                int u_local = warp_m * 32 + mf * 16 + h * 8 + (lane >> 2);
                red[warp_n * 128 + u_local] = make_float2(m4[mf][h], s4[mf][h]);
            }
    }
    __syncthreads();
    if (tid < 128) {
        float2 p0 = red[tid];
        float2 p1 = red[128 + tid];
        float mv = fmaxf(p0.x, p1.x);
        float sv = p0.y + p1.y;
        int u = uh * 128 + tid;
        int vi = (b * KK + i) * TT + u;
        g_w[vi] = g_v[vi] / (sv + __expf(mv));
    }
}

// ---------------- combine: out_pre[b,j,u] = sum_i w[b,i,u] * z[b,i,u,j'] ----------------
// z rows are j-PERMUTED: within each 16-half2 window, logical j2 = (p2&3)*4 + (p2>>2).
__global__ void __launch_bounds__(512) combine_kernel() {
    __shared__ float ws[2][KK];
    int u0 = blockIdx.x * 2, b = blockIdx.y;
    int tid = threadIdx.x;
    for (int idx = tid; idx < 2 * KK; idx += 512)
        ws[idx >> 9][idx & 511] = g_w[(b * KK + (idx & 511)) * TT + u0 + (idx >> 9)];
    __syncthreads();

    int uo = tid >> 8, jh = tid & 255;
    int u = u0 + uo;
    const __half2* zp = reinterpret_cast<const __half2*>(g_z)
                        + ((size_t)(b * KK * TT + u)) * (QQ / 2) + jh;
    const float* wsu = ws[uo];
    float accx = 0.f, accy = 0.f;
#pragma unroll 8
    for (int i = 0; i < KK; i++) {
        __half2 zz = __ldcs(zp);
        float2 zf = __half22float2(zz);
        float wv = wsu[i];
        accx += wv * zf.x;
        accy += wv * zf.y;
        zp += (size_t)TT * (QQ / 2);
    }
    // invert the store permutation: stored half2 index jh -> logical j2
    int j2 = (jh & ~15) | (((jh & 3) << 2) | ((jh >> 2) & 3));
    int j = j2 * 2;
    g_opre[(b * QQ + j) * TT + u]     = accx;
    g_opre[(b * QQ + j + 1) * TT + u] = accy;
}

// ---------------- launch ----------------
extern "C" void kernel_launch(void* const* d_in, const int* in_sizes, int n_in,
                              void* d_out, int out_size) {
    const float* q_t = (const float*)d_in[0];
    const float* k_t = (const float*)d_in[1];
    const float* v_t = (const float*)d_in[2];
    const float* Wk  = (const float*)d_in[3];
    const float* Wq  = (const float*)d_in[4];
    const float* Wva = (const float*)d_in[5];
    const float* Wal = (const float*)d_in[6];
    const float* Wvo = (const float*)d_in[7];
    float* out = (float*)d_out;

    cudaFuncSetAttribute(attn_core, cudaFuncAttributeMaxDynamicSharedMemorySize, S_TOTAL);

    proj3_kernel<<<dim3(32, 4, 3), 256>>>(q_t, k_t, v_t, Wk, Wq, Wva);

    attn_core<<<BB * KK * 2, 256, S_TOTAL>>>(Wal);

    combine_kernel<<<dim3(QQ / 4, BB), 512>>>();

    projo_kernel<<<dim3(32, 8), 256>>>(Wvo, out);
}

// round 15
// speedup vs baseline: 1.1818x; 1.0172x over previous
#include <cuda_runtime.h>
#include <cuda_fp16.h>
#include <cstdint>
#include <cstddef>

#define BB 2
#define QQ 512
#define KK 512
#define TT 256

// ---------------- scratch (device globals; no allocation) ----------------
__device__ __half g_z[(size_t)BB * KK * TT * QQ];   // [b][i][u][j']  j-permuted (4x4 transpose per 16-half2 window)
__device__ float  g_kproj[BB * KK * TT];            // k projection (fp32)
__device__ __half g_qh[BB * QQ * TT];               // q projection, PRE-SWIZZLED 64j-chunk layout
__device__ float  g_v[BB * KK * TT];                // v projection (fp32)
__device__ float  g_w[BB * KK * TT];                // v / (sum|z| + e^m)
__device__ float  g_opre[BB * QQ * TT];             // pre-Wvo output

#define DINL __device__ __forceinline__

DINL uint32_t smem_u32(const void* p) {
    uint32_t a;
    asm("{ .reg .u64 t; cvta.to.shared.u64 t, %1; cvt.u32.u64 %0, t; }" : "=r"(a) : "l"(p));
    return a;
}

DINL void ldsm4(uint32_t& r0, uint32_t& r1, uint32_t& r2, uint32_t& r3, uint32_t addr) {
    asm volatile("ldmatrix.sync.aligned.m8n8.x4.shared.b16 {%0,%1,%2,%3}, [%4];"
                 : "=r"(r0), "=r"(r1), "=r"(r2), "=r"(r3) : "r"(addr));
}

DINL void mma16816(float* c, const uint32_t* a, const uint32_t* b) {
    asm volatile(
        "mma.sync.aligned.m16n8k16.row.col.f32.f16.f16.f32 "
        "{%0,%1,%2,%3}, {%4,%5,%6,%7}, {%8,%9}, {%0,%1,%2,%3};"
        : "+f"(c[0]), "+f"(c[1]), "+f"(c[2]), "+f"(c[3])
        : "r"(a[0]), "r"(a[1]), "r"(a[2]), "r"(a[3]), "r"(b[0]), "r"(b[1]));
}

// ---- sm_90 bulk-copy + mbarrier (plain compute_103-legal PTX) ----
DINL void mbar_init(uint32_t mbar, uint32_t cnt) {
    asm volatile("mbarrier.init.shared.b64 [%0], %1;" :: "r"(mbar), "r"(cnt) : "memory");
}
DINL void mbar_expect_tx(uint32_t mbar, uint32_t bytes) {
    asm volatile("mbarrier.arrive.expect_tx.shared.b64 _, [%0], %1;"
                 :: "r"(mbar), "r"(bytes) : "memory");
}
DINL void bulk_copy_g2s(uint32_t sdst, const void* gsrc, uint32_t bytes, uint32_t mbar) {
    asm volatile(
        "cp.async.bulk.shared::cluster.global.mbarrier::complete_tx::bytes [%0], [%1], %2, [%3];"
        :: "r"(sdst), "l"(gsrc), "r"(bytes), "r"(mbar) : "memory");
}
DINL void mbar_wait(uint32_t mbar, uint32_t parity) {
    asm volatile(
        "{\n\t.reg .pred P;\n\tW%=:\n\t"
        "mbarrier.try_wait.parity.shared::cta.b64 P, [%0], %1, 0x989680;\n\t"
        "@!P bra.uni W%=;\n\t}"
        :: "r"(mbar), "r"(parity) : "memory");
}
DINL void fence_async() { asm volatile("fence.proxy.async.shared::cta;" ::: "memory"); }

DINL uint32_t pack2h(float a, float b) {
    __half2 h = __halves2half2(__float2half_rn(a), __float2half_rn(b));
    return *reinterpret_cast<uint32_t*>(&h);
}

// ---------------- projection GEMM body: out[r,u] = sum_t X[r,t]*W[u,t] ----------------
template <int MODE>
DINL void proj_body(const float* __restrict__ X, const float* __restrict__ W,
                    int rb, int ub) {
    __shared__ float xs[32][33];
    __shared__ float ws[64][33];
    int tid = threadIdx.x;
    int r = tid & 31, u0 = (tid >> 5) * 8;
    float acc[8];
#pragma unroll
    for (int e = 0; e < 8; e++) acc[e] = 0.f;

    for (int t0 = 0; t0 < TT; t0 += 32) {
#pragma unroll
        for (int l = 0; l < 4; l++) {
            int idx = tid + l * 256; int row = idx >> 5, col = idx & 31;
            xs[row][col] = X[(rb + row) * TT + t0 + col];
        }
#pragma unroll
        for (int l = 0; l < 8; l++) {
            int idx = tid + l * 256; int row = idx >> 5, col = idx & 31;
            ws[row][col] = W[(ub + row) * TT + t0 + col];
        }
        __syncthreads();
#pragma unroll
        for (int tt = 0; tt < 32; tt++) {
            float xv = xs[r][tt];
#pragma unroll
            for (int e = 0; e < 8; e++) acc[e] += xv * ws[u0 + e][tt];
        }
        __syncthreads();
    }
    if (MODE == 1) {
        // q projection -> PRE-SWIZZLED 64j-chunk layout
        int rg = rb + r;
        int bb2 = rg >> 9, j = rg & 511;
        int cch = j >> 6, rr = j & 63;
        int grp = (ub + u0) >> 3;
        uint32_t hoff = ((uint32_t)((bb2 * 8 + cch) * 64 + rr)) * 256u
                        + (uint32_t)((grp ^ (rr & 7)) << 3);
        uint4 v;
        v.x = pack2h(acc[0], acc[1]);
        v.y = pack2h(acc[2], acc[3]);
        v.z = pack2h(acc[4], acc[5]);
        v.w = pack2h(acc[6], acc[7]);
        *reinterpret_cast<uint4*>(g_qh + hoff) = v;
    } else {
#pragma unroll
        for (int e = 0; e < 8; e++) {
            int o = (rb + r) * TT + ub + u0 + e;
            if (MODE == 0)      g_kproj[o] = acc[e];
            else                g_v[o]     = acc[e];
        }
    }
}

// fused k/q/v projections: blockIdx.z selects which
__global__ void __launch_bounds__(256) proj3_kernel(const float* __restrict__ q_t,
                                                    const float* __restrict__ k_t,
                                                    const float* __restrict__ v_t,
                                                    const float* __restrict__ Wk,
                                                    const float* __restrict__ Wq,
                                                    const float* __restrict__ Wva) {
    int rb = blockIdx.x * 32, ub = blockIdx.y * 64;
    if (blockIdx.z == 0)      proj_body<0>(k_t, Wk,  rb, ub);
    else if (blockIdx.z == 1) proj_body<1>(q_t, Wq,  rb, ub);
    else                      proj_body<2>(v_t, Wva, rb, ub);
}

// final projection: out = g_opre @ Wvo^T — 32x32 tiles, 256 blocks
__global__ void __launch_bounds__(256) projo_kernel(const float* __restrict__ W,
                                                    float* __restrict__ out_ext) {
    __shared__ float xs[32][33];
    __shared__ float ws[32][33];
    int rb = blockIdx.x * 32, ub = blockIdx.y * 32;
    int tid = threadIdx.x;
    int r = tid & 31, u0 = (tid >> 5) * 4;
    float acc[4] = {0.f, 0.f, 0.f, 0.f};

    for (int t0 = 0; t0 < TT; t0 += 32) {
#pragma unroll
        for (int l = 0; l < 4; l++) {
            int idx = tid + l * 256; int row = idx >> 5, col = idx & 31;
            xs[row][col] = g_opre[(rb + row) * TT + t0 + col];
        }
#pragma unroll
        for (int l = 0; l < 4; l++) {
            int idx = tid + l * 256; int row = idx >> 5, col = idx & 31;
            ws[row][col] = W[(ub + row) * TT + t0 + col];
        }
        __syncthreads();
#pragma unroll
        for (int tt = 0; tt < 32; tt++) {
            float xv = xs[r][tt];
#pragma unroll
            for (int e = 0; e < 4; e++) acc[e] += xv * ws[u0 + e][tt];
        }
        __syncthreads();
    }
#pragma unroll
    for (int e = 0; e < 4; e++)
        out_ext[(rb + r) * TT + ub + u0 + e] = acc[e];
}

// ---------------- core kernel ----------------
// SMEM: A slab [0,64K) persistent, B ring 4x32K at [64K,192K), mbars at 192K
#define S_BRING 65536
#define S_MB    196608
#define S_TOTAL 196672
#define CHUNK_BYTES 32768u
#define ARES 6   // ks 0..5 A fragments register-resident; ks 6..15 re-ldsm'd (pipelined)

__global__ void __launch_bounds__(256, 1) attn_core(const float* __restrict__ Wal) {
    extern __shared__ char smem[];
    uint32_t sb = smem_u32(smem);
    const int tid = threadIdx.x;
    const int lane = tid & 31;
    const int wid = tid >> 5;
    const int warp_m = wid >> 1;   // 0..3  (32 u-rows each)
    const int warp_n = wid & 1;    // 0..1  (32 j-cols each)

    const int bx = blockIdx.x;
    const int uh = bx & 1;
    const int i  = (bx >> 1) & 511;
    const int b  = bx >> 10;

    // ---- tid0: init mbarriers, then kick ALL 4 prologue copies ----
    const __half* __restrict__ qsw = g_qh + (size_t)(b * 8) * 64 * 256;
    if (tid == 0) {
#pragma unroll
        for (int m = 0; m < 4; m++) mbar_init(sb + S_MB + m * 8, 1);
        fence_async();
#pragma unroll
        for (int m = 0; m < 4; m++) {
            mbar_expect_tx(sb + S_MB + m * 8, CHUNK_BYTES);
            bulk_copy_g2s(sb + S_BRING + m * CHUNK_BYTES, qsw + (size_t)m * 64 * 256,
                          CHUNK_BYTES, sb + S_MB + m * 8);
        }
    }

    const float* __restrict__ walr = Wal + (size_t)uh * 128 * TT;
    const float* __restrict__ kp   = g_kproj + (b * KK + i) * TT;

    // ---- build A = fp16(Wal[u_half,:] * k_i[:]) in persistent smem slab ----
#pragma unroll
    for (int it = 0; it < 16; it++) {
        int idx = tid + it * 256;
        int row = idx >> 5, cc = idx & 31;
        int t0 = cc * 8;
        float4 w0 = *reinterpret_cast<const float4*>(walr + row * TT + t0);
        float4 w1 = *reinterpret_cast<const float4*>(walr + row * TT + t0 + 4);
        float4 k0 = __ldg(reinterpret_cast<const float4*>(kp + t0));
        float4 k1 = __ldg(reinterpret_cast<const float4*>(kp + t0 + 4));
        uint4 v;
        v.x = pack2h(w0.x * k0.x, w0.y * k0.y);
        v.y = pack2h(w0.z * k0.z, w0.w * k0.w);
        v.z = pack2h(w1.x * k1.x, w1.y * k1.y);
        v.w = pack2h(w1.z * k1.z, w1.w * k1.w);
        uint32_t off = (uint32_t)(row * 512 + ((cc ^ (row & 7)) << 4));
        *reinterpret_cast<uint4*>(smem + off) = v;
    }
    __syncthreads();   // A staged AND mbarriers published

    // A addressing; ks 0..ARES-1 resident in regs, ks ARES..15 re-ldsm'd (pipelined)
    const int cbitA = lane >> 4;
    uint32_t amBase[2]; int xA[2];
#pragma unroll
    for (int mf = 0; mf < 2; mf++) {
        int rowA = warp_m * 32 + mf * 16 + (lane & 15);
        amBase[mf] = sb + (uint32_t)rowA * 512;
        xA[mf] = rowA & 7;
    }
    uint32_t ahi[2][ARES * 4];   // 48 regs
#pragma unroll
    for (int mf = 0; mf < 2; mf++)
#pragma unroll
        for (int ks = 0; ks < ARES; ks++)
            ldsm4(ahi[mf][ks * 4], ahi[mf][ks * 4 + 1], ahi[mf][ks * 4 + 2], ahi[mf][ks * 4 + 3],
                  amBase[mf] + (uint32_t)(((2 * ks + cbitA) ^ xA[mf]) << 4));

    // B ldmatrix lane addressing (warp reads j in [warp_n*32, +32))
    uint32_t bBase[2]; int xB[2];
    const int cbitB = (lane >> 3) & 1;
#pragma unroll
    for (int e = 0; e < 2; e++) {
        int rowB = warp_n * 32 + e * 16 + (lane & 7) + ((lane >> 4) << 3);
        bBase[e] = (uint32_t)(rowB * 512);
        xB[e] = rowB & 7;
    }

    // z store base: PERMUTED layout — thread's 4 half2 go contiguously (16B) at (lane&3)*8
    const size_t zbase = ((size_t)((b * KK + i) * TT + uh * 128)) * QQ
                         + warp_n * 32 + (lane & 3) * 8;
    const int urow0 = warp_m * 32 + (lane >> 2);   // + mf*16 + h*8
    float m4[2][2] = {{-3.0e38f, -3.0e38f}, {-3.0e38f, -3.0e38f}};
    float s4[2][2] = {{0.f, 0.f}, {0.f, 0.f}};

    // two STATICALLY-NAMED accumulator buffers (never runtime-indexed -> stay in regs)
    float accA[2][4][4], accB[2][4][4];

    // one epilogue unit: chunk cp, (mf,h) slice -> 4 half2 packed into ONE uint4 store
    auto epi_unit = [&](int cp, const float (&a)[2][4][4], int mf, int h) {
        uint4 v;
        uint32_t* pv = &v.x;
#pragma unroll
        for (int g = 0; g < 4; g++) {
            float l0 = a[mf][g][h * 2 + 0];
            float l1 = a[mf][g][h * 2 + 1];
            float e0 = __expf(l0);
            float e1 = __expf(l1);
            s4[mf][h] = fmaf(fabsf(l0), e0, s4[mf][h]);
            s4[mf][h] = fmaf(fabsf(l1), e1, s4[mf][h]);
            m4[mf][h] = fmaxf(m4[mf][h], fmaxf(l0, l1));
            pv[g] = pack2h(l0 * e0, l1 * e1);
        }
        __half* zr = g_z + zbase + (size_t)(urow0 + mf * 16 + h * 8) * QQ + cp * 64;
        __stcs(reinterpret_cast<uint4*>(zr), v);
    };

    auto loadB = [&](uint32_t (&d)[8], int ks, uint32_t bb) {
#pragma unroll
        for (int e = 0; e < 2; e++)
            ldsm4(d[e * 4], d[e * 4 + 1], d[e * 4 + 2], d[e * 4 + 3],
                  bb + bBase[e] + (uint32_t)(((2 * ks + cbitB) ^ xB[e]) << 4));
    };
    auto loadA = [&](uint32_t (&d)[8], int ks) {
#pragma unroll
        for (int mf = 0; mf < 2; mf++)
            ldsm4(d[mf * 4], d[mf * 4 + 1], d[mf * 4 + 2], d[mf * 4 + 3],
                  amBase[mf] + (uint32_t)(((2 * ks + cbitA) ^ xA[mf]) << 4));
    };

    // MMA of chunk c into accC, epilogue of chunk cp (accP) fused, B/A ldsm
    // SOFTWARE-PIPELINED one ks ahead via compile-time double-buffer renaming.
    auto run_chunk = [&](int c, float (&accC)[2][4][4],
                         const float (&accP)[2][4][4], bool doEpi, int cp) {
        mbar_wait(sb + S_MB + (c & 3) * 8, (uint32_t)((c >> 2) & 1));
        const uint32_t bb = sb + S_BRING + (c & 3) * CHUNK_BYTES;
#pragma unroll
        for (int mf = 0; mf < 2; mf++)
#pragma unroll
            for (int g = 0; g < 4; g++)
#pragma unroll
                for (int x = 0; x < 4; x++) accC[mf][g][x] = 0.f;

        uint32_t bfr[2][8];   // B renaming buffers (indices compile-time under unroll)
        uint32_t at[2][8];    // A renaming buffers for ks >= ARES
        loadB(bfr[0], 0, bb);

#pragma unroll
        for (int ks = 0; ks < 16; ks++) {
            // prefetch for ks+1 BEFORE consuming ks (hides LDSM latency under MMA issue)
            if (ks < 15) {
                loadB(bfr[(ks + 1) & 1], ks + 1, bb);
                if (ks + 1 >= ARES) loadA(at[(ks + 1) & 1], ks + 1);
            }
            if (ks < ARES) {
#pragma unroll
                for (int mf = 0; mf < 2; mf++)
#pragma unroll
                    for (int g = 0; g < 4; g++)
                        mma16816(accC[mf][g], &ahi[mf][ks * 4], &bfr[ks & 1][2 * g]);
            } else {
#pragma unroll
                for (int mf = 0; mf < 2; mf++)
#pragma unroll
                    for (int g = 0; g < 4; g++)
                        mma16816(accC[mf][g], &at[ks & 1][mf * 4], &bfr[ks & 1][2 * g]);
            }
            if (doEpi && (ks & 3) == 3)   // fused epilogue unit (fills HMMA gaps)
                epi_unit(cp, accP, ks >> 3, (ks >> 2) & 1);
        }
    };

    // ---- pair loop: compile-time acc buffer roles; epilogue always one chunk behind ----
#pragma unroll 1
    for (int p = 0; p < 4; p++) {
        int c0 = 2 * p, c1 = 2 * p + 1;
        run_chunk(c0, accA, accB, p > 0, c0 - 1);  // epi of chunk 2p-1 (accB)
        run_chunk(c1, accB, accA, true,  c0);      // epi of chunk 2p   (accA)

        __syncthreads();   // pair buffers fully consumed by all warps
        if (p < 2 && tid == 0) {
#pragma unroll
            for (int e = 0; e < 2; e++) {
                int cn = 2 * p + 4 + e;    // refill the two freed buffers
                uint32_t mb = sb + S_MB + (cn & 3) * 8;
                mbar_expect_tx(mb, CHUNK_BYTES);
                bulk_copy_g2s(sb + S_BRING + (cn & 3) * CHUNK_BYTES,
                              qsw + (size_t)cn * 64 * 256, CHUNK_BYTES, mb);
            }
        }
    }
    // drain epilogue of chunk 7 (accB)
#pragma unroll
    for (int u = 0; u < 4; u++)
        epi_unit(7, accB, u >> 1, u & 1);

    // ---- (m,s): reduce across quad (j) then across the 2 n-warps via smem ----
#pragma unroll
    for (int mf = 0; mf < 2; mf++)
#pragma unroll
        for (int h = 0; h < 2; h++) {
#pragma unroll
            for (int off = 1; off <= 2; off <<= 1) {
                m4[mf][h] = fmaxf(m4[mf][h], __shfl_xor_sync(0xFFFFFFFFu, m4[mf][h], off));
                s4[mf][h] += __shfl_xor_sync(0xFFFFFFFFu, s4[mf][h], off);
            }
        }
    float2* red = reinterpret_cast<float2*>(smem);   // A slab dead now
    __syncthreads();
    if ((lane & 3) == 0) {
#pragma unroll
        for (int mf = 0; mf < 2; mf++)
#pragma unroll
            for (int h = 0; h < 2; h++) {
                int u_local = warp_m * 32 + mf * 16 + h * 8 + (lane >> 2);
                red[warp_n * 128 + u_local] = make_float2(m4[mf][h], s4[mf][h]);
            }
    }
    __syncthreads();
    if (tid < 128) {
        float2 p0 = red[tid];
        float2 p1 = red[128 + tid];
        float mv = fmaxf(p0.x, p1.x);
        float sv = p0.y + p1.y;
        int u = uh * 128 + tid;
        int vi = (b * KK + i) * TT + u;
        g_w[vi] = g_v[vi] / (sv + __expf(mv));
    }
}

// ---------------- combine: out_pre[b,j,u] = sum_i w[b,i,u] * z[b,i,u,j'] ----------------
// z rows are j-PERMUTED: within each 16-half2 window, logical j2 = (p2&3)*4 + (p2>>2).
__global__ void __launch_bounds__(512) combine_kernel() {
    __shared__ float ws[2][KK];
    int u0 = blockIdx.x * 2, b = blockIdx.y;
    int tid = threadIdx.x;
    for (int idx = tid; idx < 2 * KK; idx += 512)
        ws[idx >> 9][idx & 511] = g_w[(b * KK + (idx & 511)) * TT + u0 + (idx >> 9)];
    __syncthreads();

    int uo = tid >> 8, jh = tid & 255;
    int u = u0 + uo;
    const __half2* zp = reinterpret_cast<const __half2*>(g_z)
                        + ((size_t)(b * KK * TT + u)) * (QQ / 2) + jh;
    const float* wsu = ws[uo];
    float accx = 0.f, accy = 0.f;
#pragma unroll 8
    for (int i = 0; i < KK; i++) {
        __half2 zz = __ldcs(zp);
        float2 zf = __half22float2(zz);
        float wv = wsu[i];
        accx += wv * zf.x;
        accy += wv * zf.y;
        zp += (size_t)TT * (QQ / 2);
    }
    // invert the store permutation: stored half2 index jh -> logical j2
    int j2 = (jh & ~15) | (((jh & 3) << 2) | ((jh >> 2) & 3));
    int j = j2 * 2;
    g_opre[(b * QQ + j) * TT + u]     = accx;
    g_opre[(b * QQ + j + 1) * TT + u] = accy;
}

// ---------------- launch ----------------
extern "C" void kernel_launch(void* const* d_in, const int* in_sizes, int n_in,
                              void* d_out, int out_size) {
    const float* q_t = (const float*)d_in[0];
    const float* k_t = (const float*)d_in[1];
    const float* v_t = (const float*)d_in[2];
    const float* Wk  = (const float*)d_in[3];
    const float* Wq  = (const float*)d_in[4];
    const float* Wva = (const float*)d_in[5];
    const float* Wal = (const float*)d_in[6];
    const float* Wvo = (const float*)d_in[7];
    float* out = (float*)d_out;

    cudaFuncSetAttribute(attn_core, cudaFuncAttributeMaxDynamicSharedMemorySize, S_TOTAL);

    proj3_kernel<<<dim3(32, 4, 3), 256>>>(q_t, k_t, v_t, Wk, Wq, Wva);

    attn_core<<<BB * KK * 2, 256, S_TOTAL>>>(Wal);

    combine_kernel<<<dim3(QQ / 4, BB), 512>>>();

    projo_kernel<<<dim3(32, 8), 256>>>(Wvo, out);
}